// round 16
// baseline (speedup 1.0000x reference)
#include <cuda_runtime.h>
#include <cuda_fp16.h>
#include <math.h>
#include <stdint.h>

#define B_  4
#define S_  2048
#define D_  1024
#define H_  16
#define HD_ 64
#define M_  (B_*S_)

// ---------------- scratch ----------------
__device__ __half g_x[(size_t)M_*D_];    // activations fp16 (hidden, then ctx)
__device__ __half g_w[(size_t)4*D_*D_];  // weights fp16
__device__ __half g_q[(size_t)M_*D_];    // pre-scaled by 0.125*log2(e)
__device__ __half g_k[(size_t)M_*D_];
__device__ __half g_v[(size_t)M_*D_];
__device__ float  g_moff[(size_t)M_];    // additive key-mask: 0 or -1e5

// ---------------- asm helpers ----------------
__device__ __forceinline__ uint32_t smem_u32(const void* p) {
    uint32_t a;
    asm("{ .reg .u64 t; cvta.to.shared.u64 t, %1; cvt.u32.u64 %0, t; }" : "=r"(a) : "l"(p));
    return a;
}
#define CP_ASYNC16(dst, src) \
    asm volatile("cp.async.cg.shared.global [%0], [%1], 16;" :: "r"(dst), "l"(src))
#define CP_COMMIT() asm volatile("cp.async.commit_group;" ::: "memory")
#define CP_WAIT(n)  asm volatile("cp.async.wait_group %0;" :: "n"(n) : "memory")

#define MMA_F16(c, a, b0, b1) \
    asm volatile("mma.sync.aligned.m16n8k16.row.col.f32.f16.f16.f32 " \
        "{%0,%1,%2,%3}, {%4,%5,%6,%7}, {%8,%9}, {%0,%1,%2,%3};" \
        : "+f"((c)[0]), "+f"((c)[1]), "+f"((c)[2]), "+f"((c)[3]) \
        : "r"((a)[0]), "r"((a)[1]), "r"((a)[2]), "r"((a)[3]), "r"(b0), "r"(b1))

#define LDSM_X4(r0,r1,r2,r3, a) \
    asm volatile("ldmatrix.sync.aligned.m8n8.x4.shared.b16 {%0,%1,%2,%3}, [%4];" \
        : "=r"(r0), "=r"(r1), "=r"(r2), "=r"(r3) : "r"(a))

#define LDSM_X4_T(r0,r1,r2,r3, a) \
    asm volatile("ldmatrix.sync.aligned.m8n8.x4.trans.shared.b16 {%0,%1,%2,%3}, [%4];" \
        : "=r"(r0), "=r"(r1), "=r"(r2), "=r"(r3) : "r"(a))

__device__ __forceinline__ uint32_t pack_f16(float lo, float hi) {
    __half2 t = __floats2half2_rn(lo, hi);
    return *reinterpret_cast<uint32_t*>(&t);
}
__device__ __forceinline__ float ex2f(float x) {
    float r;
    asm("ex2.approx.ftz.f32 %0, %1;" : "=f"(r) : "f"(x));
    return r;
}

// ---------------- fp32 -> fp16 convert (masked activations) ----------------
__global__ void conv_kernel(const float* __restrict__ in, const int* __restrict__ mask,
                            __half* __restrict__ out, int n4, int use_mask)
{
    int i = blockIdx.x * blockDim.x + threadIdx.x;
    if (i >= n4) return;
    float4 v = reinterpret_cast<const float4*>(in)[i];
    if (use_mask) {
        float mv = (float)mask[i >> 8];
        v.x *= mv; v.y *= mv; v.z *= mv; v.w *= mv;
    }
    __half2 a; a.x = __float2half(v.x); a.y = __float2half(v.y);
    __half2 b; b.x = __float2half(v.z); b.y = __float2half(v.w);
    reinterpret_cast<__half2*>(out)[2*i]     = a;
    reinterpret_cast<__half2*>(out)[2*i+1]   = b;
}

// merged weight convert: grid.y selects which W
__global__ void split4_kernel(const float* __restrict__ W0, const float* __restrict__ W1,
                              const float* __restrict__ W2, const float* __restrict__ W3,
                              __half* __restrict__ wout, int n4)
{
    int i = blockIdx.x * blockDim.x + threadIdx.x;
    if (i >= n4) return;
    const int w = blockIdx.y;
    const float* in = (w == 0) ? W0 : (w == 1) ? W1 : (w == 2) ? W2 : W3;
    const size_t off = (size_t)w * n4;
    float4 v = reinterpret_cast<const float4*>(in)[i];
    __half2 a; a.x = __float2half(v.x); a.y = __float2half(v.y);
    __half2 b; b.x = __float2half(v.z); b.y = __float2half(v.w);
    reinterpret_cast<__half2*>(wout)[2*(off + i)]     = a;
    reinterpret_cast<__half2*>(wout)[2*(off + i) + 1] = b;
}

// additive mask: 0 for kept keys, -1e5 for masked
__global__ void moff_kernel(const int* __restrict__ mask, float* __restrict__ moff, int n)
{
    int i = blockIdx.x * blockDim.x + threadIdx.x;
    if (i < n) moff[i] = mask[i] ? 0.0f : -1.0e5f;
}

#define GS_A  72
#define G1_STAGE (2*128*GS_A)    // fp16 elems per stage (A, W tiles) = 18432

// ---------------- 1-pass fp16 GEMM mainloop: 3-stage, wait(1) ----------------
__device__ __forceinline__ void gemm1_issue(const __half* const srcs[2], __half* stage,
                                            int chunk, int tid)
{
#pragma unroll
    for (int it = 0; it < 8; it++) {
        int unit = tid + it*256;            // 0..2047
        int mat = unit >> 10, rem = unit & 1023;
        int row = rem >> 3,  g  = rem & 7;
        const __half* src = srcs[mat] + (size_t)row*D_ + chunk*64 + g*8;
        uint32_t dst = smem_u32(stage + mat*128*GS_A + row*GS_A + g*8);
        CP_ASYNC16(dst, src);
    }
}

__device__ __forceinline__ void mgemm1_main(
    const __half* __restrict__ A, const __half* __restrict__ W,
    int m0, int n0, int tid, __half* stg0, float acc[2][8][4])
{
    __half* stg[3] = { stg0, stg0 + G1_STAGE, stg0 + 2*G1_STAGE };
    const int lane = tid & 31;
    const int wid = tid >> 5;
    const int wr = wid >> 1;
    const int wc = wid & 1;

#pragma unroll
    for (int mt = 0; mt < 2; mt++)
#pragma unroll
        for (int n = 0; n < 8; n++)
#pragma unroll
            for (int c = 0; c < 4; c++) acc[mt][n][c] = 0.0f;

    const __half* srcs[2] = { A + (size_t)m0*D_, W + (size_t)n0*D_ };

    gemm1_issue(srcs, stg[0], 0, tid); CP_COMMIT();
    gemm1_issue(srcs, stg[1], 1, tid); CP_COMMIT();

    const int rowA = wr*32 + ((lane >> 3) & 1)*8 + (lane & 7);
    const int colA = (lane >> 4)*8;
    const int rowB = wc*64 + (lane >> 4)*8 + (lane & 7);
    const int colB = ((lane >> 3) & 1)*8;

    for (int chunk = 0; chunk < 16; chunk++) {
        if (chunk < 15) { CP_WAIT(1); } else { CP_WAIT(0); }
        __syncthreads();   // stage 'chunk' visible; stage (chunk+2)%3 drained
        if (chunk + 2 < 16) {
            gemm1_issue(srcs, stg[(chunk + 2) % 3], chunk + 2, tid);
            CP_COMMIT();
        }

        __half* As = stg[chunk % 3];
        __half* Ws = As + 128*GS_A;

#pragma unroll
        for (int kk = 0; kk < 4; kk++) {
            uint32_t ah[2][4];
#pragma unroll
            for (int mt = 0; mt < 2; mt++) {
                uint32_t a = smem_u32(As + (rowA + mt*16)*GS_A + kk*16 + colA);
                LDSM_X4(ah[mt][0], ah[mt][1], ah[mt][2], ah[mt][3], a);
            }
#pragma unroll
            for (int n4 = 0; n4 < 4; n4++) {
                uint32_t w0, w1, w2, w3;
                uint32_t a = smem_u32(Ws + (rowB + n4*16)*GS_A + kk*16 + colB);
                LDSM_X4(w0, w1, w2, w3, a);
#pragma unroll
                for (int mt = 0; mt < 2; mt++) {
                    MMA_F16(acc[mt][2*n4],   ah[mt], w0, w1);
                    MMA_F16(acc[mt][2*n4+1], ah[mt], w2, w3);
                }
            }
        }
    }
}

// merged QKV GEMM: grid.x = 24 (proj = bx>>3, ntile = bx&7)
__global__ void __launch_bounds__(256, 2) mgemm_qkv_kernel(
    const __half* __restrict__ A, const __half* __restrict__ W,
    const float* __restrict__ bq, const float* __restrict__ bk, const float* __restrict__ bv,
    __half* __restrict__ qf, __half* __restrict__ kf, __half* __restrict__ vf)
{
    extern __shared__ char smraw[];
    __shared__ float sbias[128];
    const int tid = threadIdx.x;
    const int lane = tid & 31;
    const int wid = tid >> 5;
    const int wr = wid >> 1;
    const int wc = wid & 1;
    const int proj = blockIdx.x >> 3;
    const int n0 = (blockIdx.x & 7) * 128;
    const int m0 = blockIdx.y * 128;
    const size_t WSZ = (size_t)D_ * D_;

    const float* bias = (proj == 0) ? bq : (proj == 1) ? bk : bv;
    __half* C = (proj == 0) ? qf : (proj == 1) ? kf : vf;
    // Q carries softmax scale AND log2(e) so attention can use raw ex2
    const float qscale = (proj == 0) ? 0.125f * 1.44269504088896f : 1.0f;
    if (tid < 128) sbias[tid] = bias[n0 + tid];

    float acc[2][8][4];
    mgemm1_main(A, W + proj*WSZ, m0, n0, tid, (__half*)smraw, acc);

    const int cb = (lane & 3)*2;
    const int e_loc = wc*64 + cb;
    const int h = (n0 + wc*64) >> 6;
#pragma unroll
    for (int mt = 0; mt < 2; mt++) {
#pragma unroll
        for (int half = 0; half < 2; half++) {
            const int m = m0 + wr*32 + mt*16 + half*8 + (lane >> 2);
            const int b = m >> 11, s = m & 2047;
            const size_t base = (((size_t)(b*H_ + h))*S_ + s)*HD_;
#pragma unroll
            for (int n = 0; n < 8; n++) {
                float v0 = (acc[mt][n][half*2]     + sbias[e_loc + n*8])     * qscale;
                float v1 = (acc[mt][n][half*2 + 1] + sbias[e_loc + n*8 + 1]) * qscale;
                *reinterpret_cast<uint32_t*>(C + base + n*8 + cb) = pack_f16(v0, v1);
            }
        }
    }
}

// 1-pass O-projection GEMM (fp32 out * rowmask)
__global__ void __launch_bounds__(256, 2) mgemm_o_kernel(
    const __half* __restrict__ A, const __half* __restrict__ W,
    const float* __restrict__ bias, const int* __restrict__ mask,
    float* __restrict__ Cf)
{
    extern __shared__ char smraw[];
    __shared__ float sbias[128];
    const int tid = threadIdx.x;
    const int lane = tid & 31;
    const int wid = tid >> 5;
    const int wr = wid >> 1;
    const int wc = wid & 1;
    const int m0 = blockIdx.y * 128;
    const int n0 = blockIdx.x * 128;
    if (tid < 128) sbias[tid] = bias[n0 + tid];

    float acc[2][8][4];
    mgemm1_main(A, W, m0, n0, tid, (__half*)smraw, acc);

    const int cb = (lane & 3)*2;
    const int e_loc = wc*64 + cb;
#pragma unroll
    for (int mt = 0; mt < 2; mt++) {
#pragma unroll
        for (int half = 0; half < 2; half++) {
            const int m = m0 + wr*32 + mt*16 + half*8 + (lane >> 2);
            const float maskv = (float)mask[m];
            float* outp = Cf + (size_t)m*D_ + n0;
#pragma unroll
            for (int n = 0; n < 8; n++) {
                float2 v;
                v.x = (acc[mt][n][half*2]     + sbias[e_loc + n*8])     * maskv;
                v.y = (acc[mt][n][half*2 + 1] + sbias[e_loc + n*8 + 1]) * maskv;
                *reinterpret_cast<float2*>(outp + e_loc + n*8) = v;
            }
        }
    }
}

// ---------------- fp16 attention (unchanged from R15) ----------------
#define AS_B 72
#define A_KTILE (64*AS_B)                 // fp16 elems per 64x64 tile
#define A_KTILE_B (A_KTILE*2)             // bytes
#define A_TILES_B (2*A_KTILE_B)           // K+V bytes = 18432
#define A_STAGE_B (A_TILES_B + 256)       // + fp32 mask slot (64 floats) = 18688
#define A_QTILE (128*AS_B)

__device__ __forceinline__ void attn_issue(const __half* kf, const __half* vf,
                                           const float* __restrict__ moffp,
                                           uint32_t stage_u, int kb, int tid)
{
#pragma unroll
    for (int it = 0; it < 2; it++) {
        int unit = tid + it*256;
        int row = unit >> 3, g = unit & 7;
        const size_t go = (size_t)(kb + row)*HD_ + g*8;
        const uint32_t so = (uint32_t)(row*AS_B + g*8)*2;
        CP_ASYNC16(stage_u + so, kf + go);
        CP_ASYNC16(stage_u + A_KTILE_B + so, vf + go);
    }
    if (tid < 16)
        CP_ASYNC16(stage_u + A_TILES_B + tid*16, moffp + kb + tid*4);
}

__global__ void __launch_bounds__(256, 2) mattn_kernel(const int* __restrict__ mask)
{
    extern __shared__ char smraw[];
    const uint32_t sm_u = smem_u32(smraw);
    const uint32_t stu[3] = { sm_u, sm_u + A_STAGE_B, sm_u + 2*A_STAGE_B };
    __half* Qs = (__half*)(smraw + 2*A_STAGE_B);   // Q aliases stage 2

    const int tid  = threadIdx.x;
    const int lane = tid & 31;
    const int ti   = tid >> 5;
    const int bh = blockIdx.y;
    const int b  = bh >> 4, h = bh & 15;
    const int q0 = blockIdx.x << 7;

    const __half* Kg = g_k + (size_t)bh*S_*HD_;
    const __half* Vg = g_v + (size_t)bh*S_*HD_;
    const float* moffp = g_moff + b*S_;

    attn_issue(Kg, Vg, moffp, stu[0], 0,  tid); CP_COMMIT();
    attn_issue(Kg, Vg, moffp, stu[1], 64, tid); CP_COMMIT();

    const __half* Qg = g_q + ((size_t)bh*S_ + q0)*HD_;
#pragma unroll
    for (int it = 0; it < 2; it++) {
        int unit = tid + it*256;
        int row = unit >> 3, c8 = unit & 7;
        *reinterpret_cast<uint4*>(Qs + row*AS_B + c8*8) =
            *reinterpret_cast<const uint4*>(Qg + (size_t)row*HD_ + c8*8);
        int row2 = row + 64;
        *reinterpret_cast<uint4*>(Qs + row2*AS_B + c8*8) =
            *reinterpret_cast<const uint4*>(Qg + (size_t)row2*HD_ + c8*8);
    }
    __syncthreads();

    uint32_t qf[4][4];
    {
        const int rowQ = ti*16 + ((lane >> 3) & 1)*8 + (lane & 7);
        const int colQ = (lane >> 4)*8;
        const uint32_t qb = stu[2] + (uint32_t)(rowQ*AS_B + colQ)*2;
#pragma unroll
        for (int g = 0; g < 4; g++)
            LDSM_X4(qf[g][0], qf[g][1], qf[g][2], qf[g][3], qb + g*32);
    }
    __syncthreads();

    float oc[8][4];
#pragma unroll
    for (int n = 0; n < 8; n++)
#pragma unroll
        for (int c = 0; c < 4; c++) oc[n][c] = 0.0f;
    float lp0 = 0.0f, lp1 = 0.0f;

    const uint32_t offK = (uint32_t)(((lane >> 4)*8 + (lane & 7))*AS_B + ((lane >> 3) & 1)*8)*2;
    const uint32_t offV = (uint32_t)((((lane >> 3) & 1)*8 + (lane & 7))*AS_B + (lane >> 4)*8)*2;
    const int cb = (lane & 3)*2;

    for (int kt = 0; kt < 32; kt++) {
        if (kt < 31) { CP_WAIT(1); } else { CP_WAIT(0); }
        __syncthreads();
        if (kt + 2 < 32) {
            attn_issue(Kg, Vg, moffp, stu[(kt + 2) % 3], (kt + 2) << 6, tid);
            CP_COMMIT();
        }

        const uint32_t st_u = stu[kt % 3];
        const float* kmf = (const float*)(smraw + (st_u - sm_u) + A_TILES_B);

        float sc[8][4];
#pragma unroll
        for (int n = 0; n < 8; n++)
#pragma unroll
            for (int c = 0; c < 4; c++) sc[n][c] = 0.0f;

#pragma unroll
        for (int g = 0; g < 4; g++) {
#pragma unroll
            for (int n2 = 0; n2 < 4; n2++) {
                uint32_t k0, k1, k2, k3;
                LDSM_X4(k0, k1, k2, k3,
                        st_u + offK + (uint32_t)(n2*16*AS_B + g*16)*2);
                MMA_F16(sc[2*n2],   qf[g], k0, k1);
                MMA_F16(sc[2*n2+1], qf[g], k2, k3);
            }
        }

#pragma unroll
        for (int n = 0; n < 8; n++) {
            const float2 mo = *reinterpret_cast<const float2*>(kmf + n*8 + cb);
            float p0 = ex2f(sc[n][0] + mo.x);
            float p1 = ex2f(sc[n][1] + mo.y);
            float p2 = ex2f(sc[n][2] + mo.x);
            float p3 = ex2f(sc[n][3] + mo.y);
            lp0 += p0 + p1;
            lp1 += p2 + p3;
            sc[n][0] = p0; sc[n][1] = p1; sc[n][2] = p2; sc[n][3] = p3;
        }

#pragma unroll
        for (int g = 0; g < 4; g++) {
            uint32_t pf[4];
#pragma unroll
            for (int nn = 0; nn < 2; nn++) {
                const int n = 2*g + nn;
                pf[nn*2]     = pack_f16(sc[n][0], sc[n][1]);
                pf[nn*2 + 1] = pack_f16(sc[n][2], sc[n][3]);
            }
#pragma unroll
            for (int d2 = 0; d2 < 4; d2++) {
                uint32_t v0, v1, v2, v3;
                LDSM_X4_T(v0, v1, v2, v3,
                          st_u + A_KTILE_B + offV + (uint32_t)(g*16*AS_B + d2*16)*2);
                MMA_F16(oc[2*d2],   pf, v0, v1);
                MMA_F16(oc[2*d2+1], pf, v2, v3);
            }
        }
    }

    lp0 += __shfl_xor_sync(0xffffffffu, lp0, 1);
    lp0 += __shfl_xor_sync(0xffffffffu, lp0, 2);
    lp1 += __shfl_xor_sync(0xffffffffu, lp1, 1);
    lp1 += __shfl_xor_sync(0xffffffffu, lp1, 2);
    const float inv0 = (lp0 > 0.f) ? (1.0f / lp0) : 0.f;
    const float inv1 = (lp1 > 0.f) ? (1.0f / lp1) : 0.f;

    const int row0 = q0 + ti*16 + (lane >> 2);
    const size_t base0 = ((size_t)(b*S_ + row0))*D_ + h*HD_ + cb;
    const size_t base1 = base0 + 8*(size_t)D_;
#pragma unroll
    for (int n = 0; n < 8; n++) {
        *reinterpret_cast<uint32_t*>(g_x + base0 + n*8) =
            pack_f16(oc[n][0]*inv0, oc[n][1]*inv0);
        *reinterpret_cast<uint32_t*>(g_x + base1 + n*8) =
            pack_f16(oc[n][2]*inv1, oc[n][3]*inv1);
    }
}

// ---------------- launch ----------------
extern "C" void kernel_launch(void* const* d_in, const int* in_sizes, int n_in,
                              void* d_out, int out_size)
{
    const float* hidden = (const float*)d_in[0];
    const int*   mask   = (const int*)d_in[1];
    const float* Wq = (const float*)d_in[2];
    const float* bq = (const float*)d_in[3];
    const float* Wk = (const float*)d_in[4];
    const float* bk = (const float*)d_in[5];
    const float* Wv = (const float*)d_in[6];
    const float* bv = (const float*)d_in[7];
    const float* Wo = (const float*)d_in[8];
    const float* bo = (const float*)d_in[9];
    float* out = (float*)d_out;

    __half *xf, *wf, *qf, *kf, *vf;
    float* moff;
    cudaGetSymbolAddress((void**)&xf, g_x);
    cudaGetSymbolAddress((void**)&wf, g_w);
    cudaGetSymbolAddress((void**)&qf, g_q);
    cudaGetSymbolAddress((void**)&kf, g_k);
    cudaGetSymbolAddress((void**)&vf, g_v);
    cudaGetSymbolAddress((void**)&moff, g_moff);

    const size_t WSZ = (size_t)D_ * D_;
    const int xn4 = (M_ * D_) / 4;
    const int wn4 = (D_ * D_) / 4;

    conv_kernel<<<(xn4 + 255)/256, 256>>>(hidden, mask, xf, xn4, 1);
    split4_kernel<<<dim3((wn4 + 255)/256, 4), 256>>>(Wq, Wk, Wv, Wo, wf, wn4);
    moff_kernel<<<(M_ + 255)/256, 256>>>(mask, moff, M_);

    const int g1smem = 3 * G1_STAGE * (int)sizeof(__half);   // 110592
    cudaFuncSetAttribute(mgemm_qkv_kernel, cudaFuncAttributeMaxDynamicSharedMemorySize, g1smem);
    cudaFuncSetAttribute(mgemm_o_kernel,   cudaFuncAttributeMaxDynamicSharedMemorySize, g1smem);

    mgemm_qkv_kernel<<<dim3(24, M_/128), 256, g1smem>>>(
        xf, wf, bq, bk, bv, qf, kf, vf);

    const int asmem = 3 * A_STAGE_B;   // 56064
    cudaFuncSetAttribute(mattn_kernel, cudaFuncAttributeMaxDynamicSharedMemorySize, asmem);
    mattn_kernel<<<dim3(S_/128, B_*H_), 256, asmem>>>(mask);

    mgemm_o_kernel<<<dim3(D_/128, M_/128), 256, g1smem>>>(
        xf, wf + 3*WSZ, bo, mask, out);
}

// round 17
// speedup vs baseline: 1.0209x; 1.0209x over previous
#include <cuda_runtime.h>
#include <cuda_fp16.h>
#include <math.h>
#include <stdint.h>

#define B_  4
#define S_  2048
#define D_  1024
#define H_  16
#define HD_ 64
#define M_  (B_*S_)

// ---------------- scratch ----------------
__device__ __half g_x[(size_t)M_*D_];    // activations fp16 (hidden, then ctx)
__device__ __half g_w[(size_t)4*D_*D_];  // weights fp16
__device__ __half g_q[(size_t)M_*D_];    // pre-scaled by 0.125*log2(e)
__device__ __half g_k[(size_t)M_*D_];
__device__ __half g_v[(size_t)M_*D_];
__device__ float  g_moff[(size_t)M_];    // additive key-mask: 0 or -1e5

// ---------------- asm helpers ----------------
__device__ __forceinline__ uint32_t smem_u32(const void* p) {
    uint32_t a;
    asm("{ .reg .u64 t; cvta.to.shared.u64 t, %1; cvt.u32.u64 %0, t; }" : "=r"(a) : "l"(p));
    return a;
}
#define CP_ASYNC16(dst, src) \
    asm volatile("cp.async.cg.shared.global [%0], [%1], 16;" :: "r"(dst), "l"(src))
#define CP_COMMIT() asm volatile("cp.async.commit_group;" ::: "memory")
#define CP_WAIT(n)  asm volatile("cp.async.wait_group %0;" :: "n"(n) : "memory")

#define MMA_F16(c, a, b0, b1) \
    asm volatile("mma.sync.aligned.m16n8k16.row.col.f32.f16.f16.f32 " \
        "{%0,%1,%2,%3}, {%4,%5,%6,%7}, {%8,%9}, {%0,%1,%2,%3};" \
        : "+f"((c)[0]), "+f"((c)[1]), "+f"((c)[2]), "+f"((c)[3]) \
        : "r"((a)[0]), "r"((a)[1]), "r"((a)[2]), "r"((a)[3]), "r"(b0), "r"(b1))

#define LDSM_X4(r0,r1,r2,r3, a) \
    asm volatile("ldmatrix.sync.aligned.m8n8.x4.shared.b16 {%0,%1,%2,%3}, [%4];" \
        : "=r"(r0), "=r"(r1), "=r"(r2), "=r"(r3) : "r"(a))

#define LDSM_X4_T(r0,r1,r2,r3, a) \
    asm volatile("ldmatrix.sync.aligned.m8n8.x4.trans.shared.b16 {%0,%1,%2,%3}, [%4];" \
        : "=r"(r0), "=r"(r1), "=r"(r2), "=r"(r3) : "r"(a))

__device__ __forceinline__ uint32_t pack_f16(float lo, float hi) {
    __half2 t = __floats2half2_rn(lo, hi);
    return *reinterpret_cast<uint32_t*>(&t);
}
__device__ __forceinline__ float ex2f(float x) {
    float r;
    asm("ex2.approx.ftz.f32 %0, %1;" : "=f"(r) : "f"(x));
    return r;
}

// ---------------- fp32 -> fp16 convert (masked activations) + moff ----------------
__global__ void conv_kernel(const float* __restrict__ in, const int* __restrict__ mask,
                            __half* __restrict__ out, float* __restrict__ moff,
                            int n4, int use_mask)
{
    int i = blockIdx.x * blockDim.x + threadIdx.x;
    if (i >= n4) return;
    float4 v = reinterpret_cast<const float4*>(in)[i];
    if (use_mask) {
        float mv = (float)mask[i >> 8];
        v.x *= mv; v.y *= mv; v.z *= mv; v.w *= mv;
    }
    __half2 a; a.x = __float2half(v.x); a.y = __float2half(v.y);
    __half2 b; b.x = __float2half(v.z); b.y = __float2half(v.w);
    reinterpret_cast<__half2*>(out)[2*i]     = a;
    reinterpret_cast<__half2*>(out)[2*i+1]   = b;
    if (moff && i < M_/4) {
        int4 mi = reinterpret_cast<const int4*>(mask)[i];
        float4 mo;
        mo.x = mi.x ? 0.0f : -1.0e5f;
        mo.y = mi.y ? 0.0f : -1.0e5f;
        mo.z = mi.z ? 0.0f : -1.0e5f;
        mo.w = mi.w ? 0.0f : -1.0e5f;
        reinterpret_cast<float4*>(moff)[i] = mo;
    }
}

// merged weight convert: grid.y selects which W
__global__ void split4_kernel(const float* __restrict__ W0, const float* __restrict__ W1,
                              const float* __restrict__ W2, const float* __restrict__ W3,
                              __half* __restrict__ wout, int n4)
{
    int i = blockIdx.x * blockDim.x + threadIdx.x;
    if (i >= n4) return;
    const int w = blockIdx.y;
    const float* in = (w == 0) ? W0 : (w == 1) ? W1 : (w == 2) ? W2 : W3;
    const size_t off = (size_t)w * n4;
    float4 v = reinterpret_cast<const float4*>(in)[i];
    __half2 a; a.x = __float2half(v.x); a.y = __float2half(v.y);
    __half2 b; b.x = __float2half(v.z); b.y = __float2half(v.w);
    reinterpret_cast<__half2*>(wout)[2*(off + i)]     = a;
    reinterpret_cast<__half2*>(wout)[2*(off + i) + 1] = b;
}

#define GS_A  72
#define G1_STAGE (2*128*GS_A)    // fp16 elems per stage (A, W tiles)

// ---------------- 1-pass fp16 GEMM mainloop: 2-stage ring (R15 config) ----------------
__device__ __forceinline__ void gemm1_issue(const __half* const srcs[2], __half* stage,
                                            int chunk, int tid)
{
#pragma unroll
    for (int it = 0; it < 8; it++) {
        int unit = tid + it*256;            // 0..2047
        int mat = unit >> 10, rem = unit & 1023;
        int row = rem >> 3,  g  = rem & 7;
        const __half* src = srcs[mat] + (size_t)row*D_ + chunk*64 + g*8;
        uint32_t dst = smem_u32(stage + mat*128*GS_A + row*GS_A + g*8);
        CP_ASYNC16(dst, src);
    }
}

__device__ __forceinline__ void mgemm1_main(
    const __half* __restrict__ A, const __half* __restrict__ W,
    int m0, int n0, int tid, __half* stg0, float acc[2][8][4])
{
    __half* stg[2] = { stg0, stg0 + G1_STAGE };
    const int lane = tid & 31;
    const int wid = tid >> 5;
    const int wr = wid >> 1;
    const int wc = wid & 1;

#pragma unroll
    for (int mt = 0; mt < 2; mt++)
#pragma unroll
        for (int n = 0; n < 8; n++)
#pragma unroll
            for (int c = 0; c < 4; c++) acc[mt][n][c] = 0.0f;

    const __half* srcs[2] = { A + (size_t)m0*D_, W + (size_t)n0*D_ };

    gemm1_issue(srcs, stg[0], 0, tid); CP_COMMIT();

    const int rowA = wr*32 + ((lane >> 3) & 1)*8 + (lane & 7);
    const int colA = (lane >> 4)*8;
    const int rowB = wc*64 + (lane >> 4)*8 + (lane & 7);
    const int colB = ((lane >> 3) & 1)*8;

    for (int chunk = 0; chunk < 16; chunk++) {
        CP_WAIT(0);
        __syncthreads();
        if (chunk + 1 < 16) {
            gemm1_issue(srcs, stg[(chunk + 1) & 1], chunk + 1, tid);
            CP_COMMIT();
        }

        __half* As = stg[chunk & 1];
        __half* Ws = As + 128*GS_A;

#pragma unroll
        for (int kk = 0; kk < 4; kk++) {
            uint32_t ah[2][4];
#pragma unroll
            for (int mt = 0; mt < 2; mt++) {
                uint32_t a = smem_u32(As + (rowA + mt*16)*GS_A + kk*16 + colA);
                LDSM_X4(ah[mt][0], ah[mt][1], ah[mt][2], ah[mt][3], a);
            }
#pragma unroll
            for (int n4 = 0; n4 < 4; n4++) {
                uint32_t w0, w1, w2, w3;
                uint32_t a = smem_u32(Ws + (rowB + n4*16)*GS_A + kk*16 + colB);
                LDSM_X4(w0, w1, w2, w3, a);
#pragma unroll
                for (int mt = 0; mt < 2; mt++) {
                    MMA_F16(acc[mt][2*n4],   ah[mt], w0, w1);
                    MMA_F16(acc[mt][2*n4+1], ah[mt], w2, w3);
                }
            }
        }
    }
}

// merged QKV GEMM: grid.x = 24 (proj = bx>>3, ntile = bx&7)
__global__ void __launch_bounds__(256, 2) mgemm_qkv_kernel(
    const __half* __restrict__ A, const __half* __restrict__ W,
    const float* __restrict__ bq, const float* __restrict__ bk, const float* __restrict__ bv,
    __half* __restrict__ qf, __half* __restrict__ kf, __half* __restrict__ vf)
{
    extern __shared__ char smraw[];
    __shared__ float sbias[128];
    const int tid = threadIdx.x;
    const int lane = tid & 31;
    const int wid = tid >> 5;
    const int wr = wid >> 1;
    const int wc = wid & 1;
    const int proj = blockIdx.x >> 3;
    const int n0 = (blockIdx.x & 7) * 128;
    const int m0 = blockIdx.y * 128;
    const size_t WSZ = (size_t)D_ * D_;

    const float* bias = (proj == 0) ? bq : (proj == 1) ? bk : bv;
    __half* C = (proj == 0) ? qf : (proj == 1) ? kf : vf;
    // Q carries softmax scale AND log2(e) so attention can use raw ex2
    const float qscale = (proj == 0) ? 0.125f * 1.44269504088896f : 1.0f;
    if (tid < 128) sbias[tid] = bias[n0 + tid];

    float acc[2][8][4];
    mgemm1_main(A, W + proj*WSZ, m0, n0, tid, (__half*)smraw, acc);

    const int cb = (lane & 3)*2;
    const int e_loc = wc*64 + cb;
    const int h = (n0 + wc*64) >> 6;
#pragma unroll
    for (int mt = 0; mt < 2; mt++) {
#pragma unroll
        for (int half = 0; half < 2; half++) {
            const int m = m0 + wr*32 + mt*16 + half*8 + (lane >> 2);
            const int b = m >> 11, s = m & 2047;
            const size_t base = (((size_t)(b*H_ + h))*S_ + s)*HD_;
#pragma unroll
            for (int n = 0; n < 8; n++) {
                float v0 = (acc[mt][n][half*2]     + sbias[e_loc + n*8])     * qscale;
                float v1 = (acc[mt][n][half*2 + 1] + sbias[e_loc + n*8 + 1]) * qscale;
                *reinterpret_cast<uint32_t*>(C + base + n*8 + cb) = pack_f16(v0, v1);
            }
        }
    }
}

// 1-pass O-projection GEMM (fp32 out * rowmask)
__global__ void __launch_bounds__(256, 2) mgemm_o_kernel(
    const __half* __restrict__ A, const __half* __restrict__ W,
    const float* __restrict__ bias, const int* __restrict__ mask,
    float* __restrict__ Cf)
{
    extern __shared__ char smraw[];
    __shared__ float sbias[128];
    const int tid = threadIdx.x;
    const int lane = tid & 31;
    const int wid = tid >> 5;
    const int wr = wid >> 1;
    const int wc = wid & 1;
    const int m0 = blockIdx.y * 128;
    const int n0 = blockIdx.x * 128;
    if (tid < 128) sbias[tid] = bias[n0 + tid];

    float acc[2][8][4];
    mgemm1_main(A, W, m0, n0, tid, (__half*)smraw, acc);

    const int cb = (lane & 3)*2;
    const int e_loc = wc*64 + cb;
#pragma unroll
    for (int mt = 0; mt < 2; mt++) {
#pragma unroll
        for (int half = 0; half < 2; half++) {
            const int m = m0 + wr*32 + mt*16 + half*8 + (lane >> 2);
            const float maskv = (float)mask[m];
            float* outp = Cf + (size_t)m*D_ + n0;
#pragma unroll
            for (int n = 0; n < 8; n++) {
                float2 v;
                v.x = (acc[mt][n][half*2]     + sbias[e_loc + n*8])     * maskv;
                v.y = (acc[mt][n][half*2 + 1] + sbias[e_loc + n*8 + 1]) * maskv;
                *reinterpret_cast<float2*>(outp + e_loc + n*8) = v;
            }
        }
    }
}

// ---------------- fp16 attention: ex2 + additive mask + ones-MMA row sums ----------------
#define AS_B 72
#define A_KTILE (64*AS_B)                 // fp16 elems per 64x64 tile
#define A_KTILE_B (A_KTILE*2)             // bytes
#define A_TILES_B (2*A_KTILE_B)           // K+V bytes = 18432
#define A_STAGE_B (A_TILES_B + 256)       // + fp32 mask slot (64 floats) = 18688
#define A_QTILE (128*AS_B)

__device__ __forceinline__ void attn_issue(const __half* kf, const __half* vf,
                                           const float* __restrict__ moffp,
                                           uint32_t stage_u, int kb, int tid)
{
#pragma unroll
    for (int it = 0; it < 2; it++) {
        int unit = tid + it*256;
        int row = unit >> 3, g = unit & 7;
        const size_t go = (size_t)(kb + row)*HD_ + g*8;
        const uint32_t so = (uint32_t)(row*AS_B + g*8)*2;
        CP_ASYNC16(stage_u + so, kf + go);
        CP_ASYNC16(stage_u + A_KTILE_B + so, vf + go);
    }
    if (tid < 16)
        CP_ASYNC16(stage_u + A_TILES_B + tid*16, moffp + kb + tid*4);
}

__global__ void __launch_bounds__(256, 2) mattn_kernel(const int* __restrict__ mask)
{
    extern __shared__ char smraw[];
    const uint32_t sm_u = smem_u32(smraw);
    const uint32_t stu[3] = { sm_u, sm_u + A_STAGE_B, sm_u + 2*A_STAGE_B };
    __half* Qs = (__half*)(smraw + 2*A_STAGE_B);   // Q aliases stage 2

    const int tid  = threadIdx.x;
    const int lane = tid & 31;
    const int ti   = tid >> 5;
    const int bh = blockIdx.y;
    const int b  = bh >> 4, h = bh & 15;
    const int q0 = blockIdx.x << 7;

    const __half* Kg = g_k + (size_t)bh*S_*HD_;
    const __half* Vg = g_v + (size_t)bh*S_*HD_;
    const float* moffp = g_moff + b*S_;

    attn_issue(Kg, Vg, moffp, stu[0], 0,  tid); CP_COMMIT();
    attn_issue(Kg, Vg, moffp, stu[1], 64, tid); CP_COMMIT();

    const __half* Qg = g_q + ((size_t)bh*S_ + q0)*HD_;
#pragma unroll
    for (int it = 0; it < 2; it++) {
        int unit = tid + it*256;
        int row = unit >> 3, c8 = unit & 7;
        *reinterpret_cast<uint4*>(Qs + row*AS_B + c8*8) =
            *reinterpret_cast<const uint4*>(Qg + (size_t)row*HD_ + c8*8);
        int row2 = row + 64;
        *reinterpret_cast<uint4*>(Qs + row2*AS_B + c8*8) =
            *reinterpret_cast<const uint4*>(Qg + (size_t)row2*HD_ + c8*8);
    }
    __syncthreads();

    uint32_t qf[4][4];
    {
        const int rowQ = ti*16 + ((lane >> 3) & 1)*8 + (lane & 7);
        const int colQ = (lane >> 4)*8;
        const uint32_t qb = stu[2] + (uint32_t)(rowQ*AS_B + colQ)*2;
#pragma unroll
        for (int g = 0; g < 4; g++)
            LDSM_X4(qf[g][0], qf[g][1], qf[g][2], qf[g][3], qb + g*32);
    }
    __syncthreads();

    float oc[8][4];
#pragma unroll
    for (int n = 0; n < 8; n++)
#pragma unroll
        for (int c = 0; c < 4; c++) oc[n][c] = 0.0f;
    float lq[4] = {0.f, 0.f, 0.f, 0.f};           // row-sum accumulator (ones-MMA)
    const uint32_t ONES = 0x3C003C00u;            // (1.0h, 1.0h)

    const uint32_t offK = (uint32_t)(((lane >> 4)*8 + (lane & 7))*AS_B + ((lane >> 3) & 1)*8)*2;
    const uint32_t offV = (uint32_t)((((lane >> 3) & 1)*8 + (lane & 7))*AS_B + (lane >> 4)*8)*2;
    const int cb = (lane & 3)*2;

    for (int kt = 0; kt < 32; kt++) {
        if (kt < 31) { CP_WAIT(1); } else { CP_WAIT(0); }
        __syncthreads();
        if (kt + 2 < 32) {
            attn_issue(Kg, Vg, moffp, stu[(kt + 2) % 3], (kt + 2) << 6, tid);
            CP_COMMIT();
        }

        const uint32_t st_u = stu[kt % 3];
        const float* kmf = (const float*)(smraw + (st_u - sm_u) + A_TILES_B);

        // ---- S (log2-domain) = Q K^T ----
        float sc[8][4];
#pragma unroll
        for (int n = 0; n < 8; n++)
#pragma unroll
            for (int c = 0; c < 4; c++) sc[n][c] = 0.0f;

#pragma unroll
        for (int g = 0; g < 4; g++) {
#pragma unroll
            for (int n2 = 0; n2 < 4; n2++) {
                uint32_t k0, k1, k2, k3;
                LDSM_X4(k0, k1, k2, k3,
                        st_u + offK + (uint32_t)(n2*16*AS_B + g*16)*2);
                MMA_F16(sc[2*n2],   qf[g], k0, k1);
                MMA_F16(sc[2*n2+1], qf[g], k2, k3);
            }
        }

        // ---- P = ex2(s + moff): 1 MUFU per element, additive mask ----
#pragma unroll
        for (int n = 0; n < 8; n++) {
            const float2 mo = *reinterpret_cast<const float2*>(kmf + n*8 + cb);
            sc[n][0] = ex2f(sc[n][0] + mo.x);
            sc[n][1] = ex2f(sc[n][1] + mo.y);
            sc[n][2] = ex2f(sc[n][2] + mo.x);
            sc[n][3] = ex2f(sc[n][3] + mo.y);
        }

        // ---- pack P + PV + ones-MMA row sums ----
#pragma unroll
        for (int g = 0; g < 4; g++) {
            uint32_t pf[4];
#pragma unroll
            for (int nn = 0; nn < 2; nn++) {
                const int n = 2*g + nn;
                pf[nn*2]     = pack_f16(sc[n][0], sc[n][1]);
                pf[nn*2 + 1] = pack_f16(sc[n][2], sc[n][3]);
            }
            MMA_F16(lq, pf, ONES, ONES);   // row sums over this key group
#pragma unroll
            for (int d2 = 0; d2 < 4; d2++) {
                uint32_t v0, v1, v2, v3;
                LDSM_X4_T(v0, v1, v2, v3,
                          st_u + A_KTILE_B + offV + (uint32_t)(g*16*AS_B + d2*16)*2);
                MMA_F16(oc[2*d2],   pf, v0, v1);
                MMA_F16(oc[2*d2+1], pf, v2, v3);
            }
        }
    }

    const float inv0 = (lq[0] > 0.f) ? (1.0f / lq[0]) : 0.f;
    const float inv1 = (lq[2] > 0.f) ? (1.0f / lq[2]) : 0.f;

    // ctx written as single fp16 (O-projection is 1-pass)
    const int row0 = q0 + ti*16 + (lane >> 2);
    const size_t base0 = ((size_t)(b*S_ + row0))*D_ + h*HD_ + cb;
    const size_t base1 = base0 + 8*(size_t)D_;
#pragma unroll
    for (int n = 0; n < 8; n++) {
        *reinterpret_cast<uint32_t*>(g_x + base0 + n*8) =
            pack_f16(oc[n][0]*inv0, oc[n][1]*inv0);
        *reinterpret_cast<uint32_t*>(g_x + base1 + n*8) =
            pack_f16(oc[n][2]*inv1, oc[n][3]*inv1);
    }
}

// ---------------- launch ----------------
extern "C" void kernel_launch(void* const* d_in, const int* in_sizes, int n_in,
                              void* d_out, int out_size)
{
    const float* hidden = (const float*)d_in[0];
    const int*   mask   = (const int*)d_in[1];
    const float* Wq = (const float*)d_in[2];
    const float* bq = (const float*)d_in[3];
    const float* Wk = (const float*)d_in[4];
    const float* bk = (const float*)d_in[5];
    const float* Wv = (const float*)d_in[6];
    const float* bv = (const float*)d_in[7];
    const float* Wo = (const float*)d_in[8];
    const float* bo = (const float*)d_in[9];
    float* out = (float*)d_out;

    __half *xf, *wf, *qf, *kf, *vf;
    float* moff;
    cudaGetSymbolAddress((void**)&xf, g_x);
    cudaGetSymbolAddress((void**)&wf, g_w);
    cudaGetSymbolAddress((void**)&qf, g_q);
    cudaGetSymbolAddress((void**)&kf, g_k);
    cudaGetSymbolAddress((void**)&vf, g_v);
    cudaGetSymbolAddress((void**)&moff, g_moff);

    const size_t WSZ = (size_t)D_ * D_;
    const int xn4 = (M_ * D_) / 4;
    const int wn4 = (D_ * D_) / 4;

    conv_kernel<<<(xn4 + 255)/256, 256>>>(hidden, mask, xf, moff, xn4, 1);
    split4_kernel<<<dim3((wn4 + 255)/256, 4), 256>>>(Wq, Wk, Wv, Wo, wf, wn4);

    const int g1smem = 2 * G1_STAGE * (int)sizeof(__half);   // 73728
    cudaFuncSetAttribute(mgemm_qkv_kernel, cudaFuncAttributeMaxDynamicSharedMemorySize, g1smem);
    cudaFuncSetAttribute(mgemm_o_kernel,   cudaFuncAttributeMaxDynamicSharedMemorySize, g1smem);

    mgemm_qkv_kernel<<<dim3(24, M_/128), 256, g1smem>>>(
        xf, wf, bq, bk, bv, qf, kf, vf);

    const int asmem = 3 * A_STAGE_B;   // 56064
    cudaFuncSetAttribute(mattn_kernel, cudaFuncAttributeMaxDynamicSharedMemorySize, asmem);
    mattn_kernel<<<dim3(S_/128, B_*H_), 256, asmem>>>(mask);

    mgemm_o_kernel<<<dim3(D_/128, M_/128), 256, g1smem>>>(
        xf, wf + 3*WSZ, bo, mask, out);
}